// round 16
// baseline (speedup 1.0000x reference)
#include <cuda_runtime.h>
#include <cstdint>

// Problem constants
#define BATCH 32
#define CH    64
#define HW    128
#define CHW   (HW*HW)
#define NK    4
#define TAPS  9
#define CIK   (CH*TAPS)          // 576
#define CI_CHUNK 4
#define NCHUNK  (CH/CI_CHUNK)    // 16
#define WCHUNK  (CI_CHUNK*CIK)   // 2304 floats per weight chunk
#define WLINES  (WCHUNK/4)       // 576 16B lines per weight chunk

// Scratch (device globals: no allocation allowed)
// g_wmix layout: [b][ci][tap][co]  (co contiguous)
__device__ float g_wmix[BATCH * CH * TAPS * CH];
__device__ float g_bmix[BATCH * CH];

// ---------------------------------------------------------------------------
// Kernel 1: mix weight bank + bias per sample
// ---------------------------------------------------------------------------
__global__ void __launch_bounds__(256) mix_kernel(
    const float* __restrict__ att,     // [B, NK]
    const float* __restrict__ weight,  // [NK, C, C, 3, 3]
    const float* __restrict__ bias)    // [NK, C]
{
    int gid = blockIdx.x * 256 + threadIdx.x;
    const int TOT = BATCH * CH * TAPS * CH;
    if (gid < TOT) {
        int b    = gid / (CH * TAPS * CH);
        int rem  = gid - b * (CH * TAPS * CH);
        int ci   = rem / (TAPS * CH);
        int rem2 = rem - ci * (TAPS * CH);
        int tap  = rem2 >> 6;
        int co   = rem2 & 63;

        float a0 = att[b * NK + 0];
        float a1 = att[b * NK + 1];
        float a2 = att[b * NK + 2];
        float a3 = att[b * NK + 3];

        int base   = ((co * CH) + ci) * TAPS + tap;
        int stride = CH * CH * TAPS;
        g_wmix[gid] = a0 * weight[base]
                    + a1 * weight[base + stride]
                    + a2 * weight[base + 2 * stride]
                    + a3 * weight[base + 3 * stride];
    }
    if (gid < BATCH * CH) {
        int b  = gid >> 6;
        int co = gid & 63;
        float s = 0.f;
        #pragma unroll
        for (int k = 0; k < NK; k++)
            s += att[b * NK + k] * bias[k * CH + co];
        g_bmix[gid] = s;
    }
}

// ---------------------------------------------------------------------------
// Kernel 2: direct 3x3 conv, FFMA2 paired over c_out, 8 c_out per thread.
// One CTA per (b, y). 128 threads: co0=(tx>>4)*8, w0=(tx&15)*8.
// Affine cp.async staging (borders are chunk-invariant zeros, zeroed once).
// Weights staged with 16B cp.async.cg (5/thread/chunk). Compute walks the
// 12 windows (4 ci x 3 rows, contiguous in smem) with a 2-deep software
// pipeline: next window's LDS issued during current window's 48 FFMA2.
// ---------------------------------------------------------------------------

typedef unsigned long long u64;

__device__ __forceinline__ u64 ffma2(u64 d, u64 a, u64 b) {
    asm("fma.rn.f32x2 %0, %1, %2, %0;" : "+l"(d) : "l"(a), "l"(b));
    return d;
}
__device__ __forceinline__ u64 dup2(float v) {
    u64 p;
    asm("mov.b64 %0, {%1, %1};" : "=l"(p) : "f"(v));
    return p;
}
__device__ __forceinline__ void cp_async4(unsigned saddr, const float* gaddr) {
    asm volatile("cp.async.ca.shared.global [%0], [%1], 4;"
                 :: "r"(saddr), "l"(gaddr));
}
__device__ __forceinline__ void cp_async16(unsigned saddr, const float* gaddr) {
    asm volatile("cp.async.cg.shared.global [%0], [%1], 16;"
                 :: "r"(saddr), "l"(gaddr));
}
__device__ __forceinline__ void cp_async_commit() {
    asm volatile("cp.async.commit_group;" ::: "memory");
}
__device__ __forceinline__ void cp_async_wait0() {
    asm volatile("cp.async.wait_group 0;" ::: "memory");
}

// Plain-float padded row: insert 4-float pad every 32 floats.
#define XR 148   // row stride in floats (16B multiple)
__device__ __forceinline__ int XIDX4(int c) { return c + ((c >> 5) << 2); }

__global__ void __launch_bounds__(128, 4) conv_kernel(
    const float* __restrict__ x,   // [B, C, H, W]
    float* __restrict__ out)       // [B, C, H, W]
{
    __shared__ alignas(16) float xin[2][CI_CHUNK * 3 * XR];  // 14.2 KB
    __shared__ alignas(16) float wsf[2][WCHUNK];             // 18.4 KB

    const int y  = blockIdx.x;
    const int b  = blockIdx.y;
    const int tx = threadIdx.x;

    const int co0 = (tx >> 4) << 3;  // 0..56 step 8
    const int w0  = (tx & 15) << 3;  // 0..120 step 8

    // LDS float offsets for the 3 loads of the 10-float window
    const int xo0 = XIDX4(w0);
    const int xo1 = XIDX4(w0 + 4);
    const int xo2 = XIDX4(w0 + 8);

    // Row validity (y-borders): staged rows cover input rows y-1, y, y+1
    const bool vr0 = (y > 0);
    const bool vr2 = (y < HW - 1);
    const int  yo0 = (y - 1) * HW + tx;   // guarded by vr0
    const int  yo1 =  y      * HW + tx;
    const int  yo2 = (y + 1) * HW + tx;

    // Affine smem destination base for this thread's column (c = tx+1)
    const unsigned scol = (unsigned)(XIDX4(tx + 1) * 4);

    // Accumulators: 4 co-pairs x 8 w, init with mixed bias
    u64 acc[4][8];
    #pragma unroll
    for (int cp = 0; cp < 4; cp++) {
        u64 bp = *reinterpret_cast<const u64*>(g_bmix + b * CH + co0 + 2 * cp);
        #pragma unroll
        for (int wi = 0; wi < 8; wi++) acc[cp][wi] = bp;
    }

    const float* xbase = x + (size_t)(b * CH) * CHW;
    const float* wbase = g_wmix + (size_t)(b * CH) * TAPS * CH;
    const unsigned xin0 = (unsigned)__cvta_generic_to_shared(&xin[0][0]);
    const unsigned xin1 = (unsigned)__cvta_generic_to_shared(&xin[1][0]);
    const unsigned wsf0 = (unsigned)__cvta_generic_to_shared(&wsf[0][0]);
    const unsigned wsf1 = (unsigned)__cvta_generic_to_shared(&wsf[1][0]);
    const bool     wex  = (tx < WLINES - 4 * 128);   // tx < 64: extra weight line

    // ---- prologue A: zero BOTH input buffers (borders/invalid rows stay 0) ----
    {
        float* base = &xin[0][0];
        const int tot = 2 * CI_CHUNK * 3 * XR;
        for (int i = tx * 4; i < tot; i += 128 * 4)
            *reinterpret_cast<float4*>(base + i) = make_float4(0.f, 0.f, 0.f, 0.f);
    }
    __syncthreads();

    // ---- prologue B: stage chunk 0 into buffer 0 ----
    {
        #pragma unroll
        for (int ci4 = 0; ci4 < CI_CHUNK; ci4++) {
            const float* xc = xbase + ci4 * CHW;
            unsigned xd = xin0 + (unsigned)(ci4 * 3 * XR * 4) + scol;
            if (vr0) cp_async4(xd,                          xc + yo0);
                     cp_async4(xd + (unsigned)(XR * 4),     xc + yo1);
            if (vr2) cp_async4(xd + (unsigned)(2 * XR * 4), xc + yo2);
        }
        #pragma unroll
        for (int k = 0; k < 4; k++)
            cp_async16(wsf0 + (tx + k * 128) * 16, wbase + (tx + k * 128) * 4);
        if (wex) cp_async16(wsf0 + (tx + 512) * 16, wbase + (tx + 512) * 4);
        cp_async_commit();
        cp_async_wait0();
    }
    __syncthreads();

    #pragma unroll 1
    for (int chunk = 0; chunk < NCHUNK; chunk++) {
        const int p = chunk & 1;
        const bool more = (chunk + 1 < NCHUNK);

        // --- prefetch next chunk entirely via cp.async (affine map) ---
        if (more) {
            const float* xc = xbase + (chunk + 1) * CI_CHUNK * CHW;
            const unsigned xd0 = (p ? xin0 : xin1) + scol;
            #pragma unroll
            for (int ci4 = 0; ci4 < CI_CHUNK; ci4++) {
                const float* xcc = xc + ci4 * CHW;
                unsigned xd = xd0 + (unsigned)(ci4 * 3 * XR * 4);
                if (vr0) cp_async4(xd,                          xcc + yo0);
                         cp_async4(xd + (unsigned)(XR * 4),     xcc + yo1);
                if (vr2) cp_async4(xd + (unsigned)(2 * XR * 4), xcc + yo2);
            }
            const float* wc = wbase + (chunk + 1) * WCHUNK;
            const unsigned wd = p ? wsf0 : wsf1;
            #pragma unroll
            for (int k = 0; k < 4; k++)
                cp_async16(wd + (tx + k * 128) * 16, wc + (tx + k * 128) * 4);
            if (wex) cp_async16(wd + (tx + 512) * 16, wc + (tx + 512) * 4);
            cp_async_commit();
        }

        // --- compute 12 windows (4 ci x 3 rows) with 2-deep LDS pipeline ---
        {
            const float* xp = xin[p];   // rows are contiguous: window w at w*XR
            const float* wp = wsf[p];

            float4 fa = *reinterpret_cast<const float4*>(xp + xo0);
            float4 fb = *reinterpret_cast<const float4*>(xp + xo1);
            float2 fc = *reinterpret_cast<const float2*>(xp + xo2);

            #pragma unroll
            for (int w = 0; w < 12; w++) {
                float4 na, nb; float2 nc;
                if (w < 11) {
                    const float* xr = xp + (w + 1) * XR;
                    na = *reinterpret_cast<const float4*>(xr + xo0);
                    nb = *reinterpret_cast<const float4*>(xr + xo1);
                    nc = *reinterpret_cast<const float2*>(xr + xo2);
                }

                u64 xw[10];
                xw[0] = dup2(fa.x); xw[1] = dup2(fa.y);
                xw[2] = dup2(fa.z); xw[3] = dup2(fa.w);
                xw[4] = dup2(fb.x); xw[5] = dup2(fb.y);
                xw[6] = dup2(fb.z); xw[7] = dup2(fb.w);
                xw[8] = dup2(fc.x); xw[9] = dup2(fc.y);

                const int ci4 = w / 3;
                const int ky  = w - 3 * ci4;
                const float* wr = wp + ci4 * CIK + ky * 3 * CH + co0;
                #pragma unroll
                for (int kx = 0; kx < 3; kx++) {
                    ulonglong2 wa  = *reinterpret_cast<const ulonglong2*>(wr + kx * CH);
                    ulonglong2 wb2 = *reinterpret_cast<const ulonglong2*>(wr + kx * CH + 4);
                    #pragma unroll
                    for (int wi = 0; wi < 8; wi++) {
                        acc[0][wi] = ffma2(acc[0][wi], wa.x,  xw[kx + wi]);
                        acc[1][wi] = ffma2(acc[1][wi], wa.y,  xw[kx + wi]);
                        acc[2][wi] = ffma2(acc[2][wi], wb2.x, xw[kx + wi]);
                        acc[3][wi] = ffma2(acc[3][wi], wb2.y, xw[kx + wi]);
                    }
                }

                fa = na; fb = nb; fc = nc;
            }
        }

        // --- drain async stages; publish buffer ---
        if (more) cp_async_wait0();
        __syncthreads();
    }

    // --- stores: 8 co x 8 w per thread ---
    union Cv { u64 u; float2 f; };
    #pragma unroll
    for (int cp = 0; cp < 4; cp++) {
        Cv v[8];
        #pragma unroll
        for (int wi = 0; wi < 8; wi++) v[wi].u = acc[cp][wi];
        #pragma unroll
        for (int half = 0; half < 2; half++) {
            int co = co0 + 2 * cp + half;
            float* o = out + (((size_t)(b * CH + co) * HW) + y) * HW + w0;
            float4 s0, s1;
            if (half == 0) {
                s0 = make_float4(v[0].f.x, v[1].f.x, v[2].f.x, v[3].f.x);
                s1 = make_float4(v[4].f.x, v[5].f.x, v[6].f.x, v[7].f.x);
            } else {
                s0 = make_float4(v[0].f.y, v[1].f.y, v[2].f.y, v[3].f.y);
                s1 = make_float4(v[4].f.y, v[5].f.y, v[6].f.y, v[7].f.y);
            }
            *reinterpret_cast<float4*>(o)     = s0;
            *reinterpret_cast<float4*>(o + 4) = s1;
        }
    }
}

// ---------------------------------------------------------------------------
// Launch. Inputs: x, attention, weight, bias_p.
// ---------------------------------------------------------------------------
extern "C" void kernel_launch(void* const* d_in, const int* in_sizes, int n_in,
                              void* d_out, int out_size)
{
    const float* x    = (const float*)d_in[0];  // [32,64,128,128]
    const float* att  = (const float*)d_in[1];  // [32,4]
    const float* wgt  = (const float*)d_in[2];  // [4,64,64,3,3]
    const float* bias = (const float*)d_in[3];  // [4,64]
    float* out = (float*)d_out;

    const int TOT = BATCH * CH * TAPS * CH;
    mix_kernel<<<(TOT + 255) / 256, 256>>>(att, wgt, bias);

    dim3 grid(HW, BATCH);  // (y, b)
    conv_kernel<<<grid, 128>>>(x, out);
}

// round 17
// speedup vs baseline: 1.0513x; 1.0513x over previous
#include <cuda_runtime.h>
#include <cstdint>

// Problem constants
#define BATCH 32
#define CH    64
#define HW    128
#define CHW   (HW*HW)
#define NK    4
#define TAPS  9
#define CIK   (CH*TAPS)          // 576
#define CI_CHUNK 4
#define NCHUNK  (CH/CI_CHUNK)    // 16
#define WCHUNK  (CI_CHUNK*CIK)   // 2304 floats per weight chunk
#define WLINES  (WCHUNK/4)       // 576 16B lines per weight chunk

// Scratch (device globals: no allocation allowed)
// g_wmix layout: [b][ci][tap][co]  (co contiguous)
__device__ float g_wmix[BATCH * CH * TAPS * CH];
__device__ float g_bmix[BATCH * CH];

// ---------------------------------------------------------------------------
// Kernel 1: mix weight bank + bias per sample
// ---------------------------------------------------------------------------
__global__ void __launch_bounds__(256) mix_kernel(
    const float* __restrict__ att,     // [B, NK]
    const float* __restrict__ weight,  // [NK, C, C, 3, 3]
    const float* __restrict__ bias)    // [NK, C]
{
    int gid = blockIdx.x * 256 + threadIdx.x;
    const int TOT = BATCH * CH * TAPS * CH;
    if (gid < TOT) {
        int b    = gid / (CH * TAPS * CH);
        int rem  = gid - b * (CH * TAPS * CH);
        int ci   = rem / (TAPS * CH);
        int rem2 = rem - ci * (TAPS * CH);
        int tap  = rem2 >> 6;
        int co   = rem2 & 63;

        float a0 = att[b * NK + 0];
        float a1 = att[b * NK + 1];
        float a2 = att[b * NK + 2];
        float a3 = att[b * NK + 3];

        int base   = ((co * CH) + ci) * TAPS + tap;
        int stride = CH * CH * TAPS;
        g_wmix[gid] = a0 * weight[base]
                    + a1 * weight[base + stride]
                    + a2 * weight[base + 2 * stride]
                    + a3 * weight[base + 3 * stride];
    }
    if (gid < BATCH * CH) {
        int b  = gid >> 6;
        int co = gid & 63;
        float s = 0.f;
        #pragma unroll
        for (int k = 0; k < NK; k++)
            s += att[b * NK + k] * bias[k * CH + co];
        g_bmix[gid] = s;
    }
}

// ---------------------------------------------------------------------------
// Kernel 2: direct 3x3 conv, FFMA2 paired over c_out, 8 c_out per thread.
// One CTA per (b, y). 128 threads: co0=(tx>>4)*8, w0=(tx&15)*8.
// R14 structure (natural scheduling, no manual window pipeline).
// Inputs: affine 4B cp.async (borders are chunk-invariant zeros, zeroed once).
// Weights: 16B cp.async.cg (5 per thread per chunk).
// 4-ci chunks, double-buffered, 1 barrier/chunk (16 total).
// ---------------------------------------------------------------------------

typedef unsigned long long u64;

__device__ __forceinline__ u64 ffma2(u64 d, u64 a, u64 b) {
    asm("fma.rn.f32x2 %0, %1, %2, %0;" : "+l"(d) : "l"(a), "l"(b));
    return d;
}
__device__ __forceinline__ u64 dup2(float v) {
    u64 p;
    asm("mov.b64 %0, {%1, %1};" : "=l"(p) : "f"(v));
    return p;
}
__device__ __forceinline__ void cp_async4(unsigned saddr, const float* gaddr) {
    asm volatile("cp.async.ca.shared.global [%0], [%1], 4;"
                 :: "r"(saddr), "l"(gaddr));
}
__device__ __forceinline__ void cp_async16(unsigned saddr, const float* gaddr) {
    asm volatile("cp.async.cg.shared.global [%0], [%1], 16;"
                 :: "r"(saddr), "l"(gaddr));
}
__device__ __forceinline__ void cp_async_commit() {
    asm volatile("cp.async.commit_group;" ::: "memory");
}
__device__ __forceinline__ void cp_async_wait0() {
    asm volatile("cp.async.wait_group 0;" ::: "memory");
}

// Plain-float padded row: insert 4-float pad every 32 floats.
#define XR 148   // row stride in floats (16B multiple)
__device__ __forceinline__ int XIDX4(int c) { return c + ((c >> 5) << 2); }

__global__ void __launch_bounds__(128, 4) conv_kernel(
    const float* __restrict__ x,   // [B, C, H, W]
    float* __restrict__ out)       // [B, C, H, W]
{
    __shared__ alignas(16) float xin[2][CI_CHUNK * 3 * XR];  // 14.2 KB
    __shared__ alignas(16) float wsf[2][WCHUNK];             // 18.4 KB

    const int y  = blockIdx.x;
    const int b  = blockIdx.y;
    const int tx = threadIdx.x;

    const int co0 = (tx >> 4) << 3;  // 0..56 step 8
    const int w0  = (tx & 15) << 3;  // 0..120 step 8

    // LDS float offsets for the 3 loads of the 10-float window
    const int xo0 = XIDX4(w0);
    const int xo1 = XIDX4(w0 + 4);
    const int xo2 = XIDX4(w0 + 8);

    // Row validity (y-borders): staged rows cover input rows y-1, y, y+1
    const bool vr0 = (y > 0);
    const bool vr2 = (y < HW - 1);
    const int  yo0 = (y - 1) * HW + tx;   // guarded by vr0
    const int  yo1 =  y      * HW + tx;
    const int  yo2 = (y + 1) * HW + tx;

    // Affine smem destination base for this thread's column (c = tx+1)
    const unsigned scol = (unsigned)(XIDX4(tx + 1) * 4);

    // Accumulators: 4 co-pairs x 8 w, init with mixed bias
    u64 acc[4][8];
    #pragma unroll
    for (int cp = 0; cp < 4; cp++) {
        u64 bp = *reinterpret_cast<const u64*>(g_bmix + b * CH + co0 + 2 * cp);
        #pragma unroll
        for (int wi = 0; wi < 8; wi++) acc[cp][wi] = bp;
    }

    const float* xbase = x + (size_t)(b * CH) * CHW;
    const float* wbase = g_wmix + (size_t)(b * CH) * TAPS * CH;
    const unsigned xin0 = (unsigned)__cvta_generic_to_shared(&xin[0][0]);
    const unsigned xin1 = (unsigned)__cvta_generic_to_shared(&xin[1][0]);
    const unsigned wsf0 = (unsigned)__cvta_generic_to_shared(&wsf[0][0]);
    const unsigned wsf1 = (unsigned)__cvta_generic_to_shared(&wsf[1][0]);
    const bool     wex  = (tx < WLINES - 4 * 128);   // tx < 64: extra weight line

    // ---- prologue A: zero BOTH input buffers (borders/invalid rows stay 0) ----
    {
        float* base = &xin[0][0];
        const int tot = 2 * CI_CHUNK * 3 * XR;
        for (int i = tx * 4; i < tot; i += 128 * 4)
            *reinterpret_cast<float4*>(base + i) = make_float4(0.f, 0.f, 0.f, 0.f);
    }
    __syncthreads();

    // ---- prologue B: stage chunk 0 into buffer 0 ----
    {
        #pragma unroll
        for (int ci4 = 0; ci4 < CI_CHUNK; ci4++) {
            const float* xc = xbase + ci4 * CHW;
            unsigned xd = xin0 + (unsigned)(ci4 * 3 * XR * 4) + scol;
            if (vr0) cp_async4(xd,                          xc + yo0);
                     cp_async4(xd + (unsigned)(XR * 4),     xc + yo1);
            if (vr2) cp_async4(xd + (unsigned)(2 * XR * 4), xc + yo2);
        }
        #pragma unroll
        for (int k = 0; k < 4; k++)
            cp_async16(wsf0 + (tx + k * 128) * 16, wbase + (tx + k * 128) * 4);
        if (wex) cp_async16(wsf0 + (tx + 512) * 16, wbase + (tx + 512) * 4);
        cp_async_commit();
        cp_async_wait0();
    }
    __syncthreads();

    #pragma unroll 1
    for (int chunk = 0; chunk < NCHUNK; chunk++) {
        const int p = chunk & 1;
        const bool more = (chunk + 1 < NCHUNK);

        // --- prefetch next chunk entirely via cp.async (affine map) ---
        if (more) {
            const float* xc = xbase + (chunk + 1) * CI_CHUNK * CHW;
            const unsigned xd0 = (p ? xin0 : xin1) + scol;
            #pragma unroll
            for (int ci4 = 0; ci4 < CI_CHUNK; ci4++) {
                const float* xcc = xc + ci4 * CHW;
                unsigned xd = xd0 + (unsigned)(ci4 * 3 * XR * 4);
                if (vr0) cp_async4(xd,                          xcc + yo0);
                         cp_async4(xd + (unsigned)(XR * 4),     xcc + yo1);
                if (vr2) cp_async4(xd + (unsigned)(2 * XR * 4), xcc + yo2);
            }
            const float* wc = wbase + (chunk + 1) * WCHUNK;
            const unsigned wd = p ? wsf0 : wsf1;
            #pragma unroll
            for (int k = 0; k < 4; k++)
                cp_async16(wd + (tx + k * 128) * 16, wc + (tx + k * 128) * 4);
            if (wex) cp_async16(wd + (tx + 512) * 16, wc + (tx + 512) * 4);
            cp_async_commit();
        }

        // --- compute 4 ci from buffer p (natural scheduling, as in R14) ---
        #pragma unroll
        for (int ci4 = 0; ci4 < CI_CHUNK; ci4++) {
            const float* wr = wsf[p] + ci4 * CIK;
            const float* xb = xin[p] + ci4 * 3 * XR;
            #pragma unroll
            for (int ky = 0; ky < 3; ky++) {
                const float* xr = xb + ky * XR;
                float4 fa = *reinterpret_cast<const float4*>(xr + xo0);
                float4 fb = *reinterpret_cast<const float4*>(xr + xo1);
                float2 fc = *reinterpret_cast<const float2*>(xr + xo2);
                u64 xw[10];
                xw[0] = dup2(fa.x); xw[1] = dup2(fa.y);
                xw[2] = dup2(fa.z); xw[3] = dup2(fa.w);
                xw[4] = dup2(fb.x); xw[5] = dup2(fb.y);
                xw[6] = dup2(fb.z); xw[7] = dup2(fb.w);
                xw[8] = dup2(fc.x); xw[9] = dup2(fc.y);
                #pragma unroll
                for (int kx = 0; kx < 3; kx++) {
                    const float* wt = wr + (ky * 3 + kx) * CH + co0;
                    ulonglong2 wa  = *reinterpret_cast<const ulonglong2*>(wt);
                    ulonglong2 wb2 = *reinterpret_cast<const ulonglong2*>(wt + 4);
                    #pragma unroll
                    for (int wi = 0; wi < 8; wi++) {
                        acc[0][wi] = ffma2(acc[0][wi], wa.x,  xw[kx + wi]);
                        acc[1][wi] = ffma2(acc[1][wi], wa.y,  xw[kx + wi]);
                        acc[2][wi] = ffma2(acc[2][wi], wb2.x, xw[kx + wi]);
                        acc[3][wi] = ffma2(acc[3][wi], wb2.y, xw[kx + wi]);
                    }
                }
            }
        }

        // --- drain async stages; publish buffer ---
        if (more) cp_async_wait0();
        __syncthreads();
    }

    // --- stores: 8 co x 8 w per thread ---
    union Cv { u64 u; float2 f; };
    #pragma unroll
    for (int cp = 0; cp < 4; cp++) {
        Cv v[8];
        #pragma unroll
        for (int wi = 0; wi < 8; wi++) v[wi].u = acc[cp][wi];
        #pragma unroll
        for (int half = 0; half < 2; half++) {
            int co = co0 + 2 * cp + half;
            float* o = out + (((size_t)(b * CH + co) * HW) + y) * HW + w0;
            float4 s0, s1;
            if (half == 0) {
                s0 = make_float4(v[0].f.x, v[1].f.x, v[2].f.x, v[3].f.x);
                s1 = make_float4(v[4].f.x, v[5].f.x, v[6].f.x, v[7].f.x);
            } else {
                s0 = make_float4(v[0].f.y, v[1].f.y, v[2].f.y, v[3].f.y);
                s1 = make_float4(v[4].f.y, v[5].f.y, v[6].f.y, v[7].f.y);
            }
            *reinterpret_cast<float4*>(o)     = s0;
            *reinterpret_cast<float4*>(o + 4) = s1;
        }
    }
}

// ---------------------------------------------------------------------------
// Launch. Inputs: x, attention, weight, bias_p.
// ---------------------------------------------------------------------------
extern "C" void kernel_launch(void* const* d_in, const int* in_sizes, int n_in,
                              void* d_out, int out_size)
{
    const float* x    = (const float*)d_in[0];  // [32,64,128,128]
    const float* att  = (const float*)d_in[1];  // [32,4]
    const float* wgt  = (const float*)d_in[2];  // [4,64,64,3,3]
    const float* bias = (const float*)d_in[3];  // [4,64]
    float* out = (float*)d_out;

    const int TOT = BATCH * CH * TAPS * CH;
    mix_kernel<<<(TOT + 255) / 256, 256>>>(att, wgt, bias);

    dim3 grid(HW, BATCH);  // (y, b)
    conv_kernel<<<grid, 128>>>(x, out);
}